// round 3
// baseline (speedup 1.0000x reference)
#include <cuda_runtime.h>
#include <math.h>
#include <stdint.h>

#define Bb 2
#define LQ 1024
#define LKV 4096
#define Hh 1024
#define NHh 16
#define HD 64
#define MQ (Bb*LQ)        // 2048
#define MKV (Bb*LKV)      // 8192
#define NROWS (Bb*NHh*LQ) // 32768
#define LN_EPS 1e-12f

#define NEG_INF __int_as_float(0xff800000)

// ---------------- scratch (device globals; no allocation) ----------------
__device__ float g_Q[MQ*Hh];
__device__ float g_K[MKV*Hh];
__device__ float g_V[MKV*Hh];
__device__ float g_ctx[MQ*Hh];
__device__ float g_y[MQ*Hh];
__device__ float g_rmax[NROWS];
__device__ float g_rinv[NROWS];

// ---------------- generic NT GEMM: out[m,n] = sum_k X[m,k]*W[n,k] + bias[n] (+res) ----
// BM=BN=128, BK=16, 256 threads, 8x8 per thread.
__global__ __launch_bounds__(256) void gemm_nt_bias(
    const float* __restrict__ X, const float* __restrict__ W,
    const float* __restrict__ bias, const float* __restrict__ res,
    float* __restrict__ out, int M, int N, int K)
{
    __shared__ float Xs[16][128];
    __shared__ float Ws[16][128];
    const int tid = threadIdx.x;
    const int tx = tid & 15, ty = tid >> 4;
    const int m0 = blockIdx.y * 128, n0 = blockIdx.x * 128;

    float acc[8][8];
#pragma unroll
    for (int i = 0; i < 8; i++)
#pragma unroll
        for (int j = 0; j < 8; j++) acc[i][j] = 0.f;

    for (int k0 = 0; k0 < K; k0 += 16) {
#pragma unroll
        for (int l = 0; l < 2; l++) {
            int idx = tid + l * 256;        // 0..511, one float4 each
            int r   = idx >> 2;             // 0..127
            int c   = (idx & 3) * 4;        // 0,4,8,12
            float4 xv = *(const float4*)&X[(size_t)(m0 + r) * K + k0 + c];
            Xs[c+0][r] = xv.x; Xs[c+1][r] = xv.y; Xs[c+2][r] = xv.z; Xs[c+3][r] = xv.w;
            float4 wv = *(const float4*)&W[(size_t)(n0 + r) * K + k0 + c];
            Ws[c+0][r] = wv.x; Ws[c+1][r] = wv.y; Ws[c+2][r] = wv.z; Ws[c+3][r] = wv.w;
        }
        __syncthreads();
#pragma unroll
        for (int k = 0; k < 16; k++) {
            float a[8], b[8];
            *(float4*)&a[0] = *(const float4*)&Xs[k][ty*8];
            *(float4*)&a[4] = *(const float4*)&Xs[k][ty*8+4];
            *(float4*)&b[0] = *(const float4*)&Ws[k][tx*8];
            *(float4*)&b[4] = *(const float4*)&Ws[k][tx*8+4];
#pragma unroll
            for (int i = 0; i < 8; i++)
#pragma unroll
                for (int j = 0; j < 8; j++)
                    acc[i][j] = fmaf(a[i], b[j], acc[i][j]);
        }
        __syncthreads();
    }

#pragma unroll
    for (int i = 0; i < 8; i++) {
        int m = m0 + ty*8 + i;
#pragma unroll
        for (int jj = 0; jj < 2; jj++) {
            int n = n0 + tx*8 + jj*4;
            float4 v;
            v.x = acc[i][jj*4+0] + bias[n+0];
            v.y = acc[i][jj*4+1] + bias[n+1];
            v.z = acc[i][jj*4+2] + bias[n+2];
            v.w = acc[i][jj*4+3] + bias[n+3];
            if (res) {
                float4 r4 = *(const float4*)&res[(size_t)m * N + n];
                v.x += r4.x; v.y += r4.y; v.z += r4.z; v.w += r4.w;
            }
            *(float4*)&out[(size_t)m * N + n] = v;
        }
    }
}

// ---------------- scores: S[b,h,q,kv] = dot(Q,K)/8, masked ----------------
// 64x64 tile per block over full HD=64. 256 threads, 4x4 per thread.
__global__ __launch_bounds__(256) void scores_kernel(
    const int* __restrict__ mask, float* __restrict__ S)
{
    const int bh = blockIdx.z;                // 0..31
    const int b = bh / NHh, h = bh % NHh;
    const int q0 = blockIdx.y * 64, kv0 = blockIdx.x * 64;

    __shared__ float Qs[HD][68];
    __shared__ float Ks[HD][68];
    const int tid = threadIdx.x;

    const float* Qbase = g_Q + ((size_t)(b*LQ  + q0 )) * Hh + h*HD;
    const float* Kbase = g_K + ((size_t)(b*LKV + kv0)) * Hh + h*HD;
#pragma unroll
    for (int l = 0; l < 4; l++) {
        int idx = tid + l * 256;      // 0..1023, one float4 each
        int r = idx >> 4;             // 0..63
        int d = (idx & 15) * 4;       // 0..60
        float4 qv = *(const float4*)&Qbase[(size_t)r * Hh + d];
        Qs[d+0][r]=qv.x; Qs[d+1][r]=qv.y; Qs[d+2][r]=qv.z; Qs[d+3][r]=qv.w;
        float4 kv = *(const float4*)&Kbase[(size_t)r * Hh + d];
        Ks[d+0][r]=kv.x; Ks[d+1][r]=kv.y; Ks[d+2][r]=kv.z; Ks[d+3][r]=kv.w;
    }
    __syncthreads();

    const int tx = tid & 15, ty = tid >> 4;
    float acc[4][4];
#pragma unroll
    for (int i = 0; i < 4; i++)
#pragma unroll
        for (int j = 0; j < 4; j++) acc[i][j] = 0.f;

#pragma unroll 16
    for (int d = 0; d < HD; d++) {
        float4 a = *(const float4*)&Qs[d][ty*4];
        float4 c = *(const float4*)&Ks[d][tx*4];
        float av[4] = {a.x,a.y,a.z,a.w};
        float bv[4] = {c.x,c.y,c.z,c.w};
#pragma unroll
        for (int i = 0; i < 4; i++)
#pragma unroll
            for (int j = 0; j < 4; j++)
                acc[i][j] = fmaf(av[i], bv[j], acc[i][j]);
    }

    float* Srow = S + (size_t)bh * LQ * LKV;
    const int kvb = kv0 + tx*4;
    int m0v = mask[b*LKV + kvb + 0];
    int m1v = mask[b*LKV + kvb + 1];
    int m2v = mask[b*LKV + kvb + 2];
    int m3v = mask[b*LKV + kvb + 3];
#pragma unroll
    for (int i = 0; i < 4; i++) {
        int q = q0 + ty*4 + i;
        float4 v;
        v.x = (m0v == 0) ? NEG_INF : acc[i][0] * 0.125f;
        v.y = (m1v == 0) ? NEG_INF : acc[i][1] * 0.125f;
        v.z = (m2v == 0) ? NEG_INF : acc[i][2] * 0.125f;
        v.w = (m3v == 0) ? NEG_INF : acc[i][3] * 0.125f;
        *(float4*)&Srow[(size_t)q * LKV + kvb] = v;
    }
}

// ---------------- per-row softmax stats ----------------
__global__ __launch_bounds__(256) void rowstats_kernel(const float* __restrict__ S)
{
    const int row = blockIdx.x;
    const float4* s4 = (const float4*)(S + (size_t)row * LKV);
    __shared__ float red[256];
    const int tid = threadIdx.x;

    float m = NEG_INF;
    for (int i = tid; i < LKV/4; i += 256) {
        float4 v = s4[i];
        m = fmaxf(m, fmaxf(fmaxf(v.x, v.y), fmaxf(v.z, v.w)));
    }
    red[tid] = m; __syncthreads();
    for (int st = 128; st > 0; st >>= 1) {
        if (tid < st) red[tid] = fmaxf(red[tid], red[tid + st]);
        __syncthreads();
    }
    m = red[0]; __syncthreads();

    float sum = 0.f;
    for (int i = tid; i < LKV/4; i += 256) {
        float4 v = s4[i];
        sum += __expf(v.x - m) + __expf(v.y - m) + __expf(v.z - m) + __expf(v.w - m);
    }
    red[tid] = sum; __syncthreads();
    for (int st = 128; st > 0; st >>= 1) {
        if (tid < st) red[tid] += red[tid + st];
        __syncthreads();
    }
    if (tid == 0) { g_rmax[row] = m; g_rinv[row] = 1.0f / red[0]; }
}

// ---------------- ctx = softmax(S) @ V ----------------
// per (b,h): M=1024 (q) x N=64 (d) x K=4096 (kv). BM=64, BN=64, BK=32.
__global__ __launch_bounds__(256) void ctx_kernel(const float* __restrict__ S)
{
    const int bh = blockIdx.y;
    const int b = bh / NHh, h = bh % NHh;
    const int q0 = blockIdx.x * 64;

    __shared__ float Pt[32][68];
    __shared__ float Vs[32][68];
    __shared__ float rm[64], ri[64];
    const int tid = threadIdx.x;
    const int rowbase = bh * LQ + q0;

    if (tid < 64) { rm[tid] = g_rmax[rowbase + tid]; ri[tid] = g_rinv[rowbase + tid]; }
    __syncthreads();

    const float* Srow = S + (size_t)rowbase * LKV;
    const float* Vbase = g_V + (size_t)(b*LKV) * Hh + h*HD;
    const int tx = tid & 15, ty = tid >> 4;

    float acc[4][4];
#pragma unroll
    for (int i = 0; i < 4; i++)
#pragma unroll
        for (int j = 0; j < 4; j++) acc[i][j] = 0.f;

    for (int kv0 = 0; kv0 < LKV; kv0 += 32) {
#pragma unroll
        for (int l = 0; l < 2; l++) {
            int idx = tid + l * 256;       // 0..511, one float4 each
            int r = idx >> 3;              // 0..63  (q row)
            int c = (idx & 7) * 4;         // 0..28  (kv in tile)
            float4 sv = *(const float4*)&Srow[(size_t)r * LKV + kv0 + c];
            float mr = rm[r], irr = ri[r];
            Pt[c+0][r] = __expf(sv.x - mr) * irr;
            Pt[c+1][r] = __expf(sv.y - mr) * irr;
            Pt[c+2][r] = __expf(sv.z - mr) * irr;
            Pt[c+3][r] = __expf(sv.w - mr) * irr;
            int vr = idx >> 4;             // 0..31 (kv)
            int vd = (idx & 15) * 4;       // 0..60 (d)
            float4 vv = *(const float4*)&Vbase[(size_t)(kv0 + vr) * Hh + vd];
            *(float4*)&Vs[vr][vd] = vv;
        }
        __syncthreads();
#pragma unroll
        for (int kk = 0; kk < 32; kk++) {
            float4 a = *(const float4*)&Pt[kk][ty*4];
            float4 c = *(const float4*)&Vs[kk][tx*4];
            float av[4] = {a.x,a.y,a.z,a.w};
            float bv[4] = {c.x,c.y,c.z,c.w};
#pragma unroll
            for (int i = 0; i < 4; i++)
#pragma unroll
                for (int j = 0; j < 4; j++)
                    acc[i][j] = fmaf(av[i], bv[j], acc[i][j]);
        }
        __syncthreads();
    }

    // ctx layout: [b, q, h*HD + d] so O-proj sees a plain [2048,1024] row-major matrix
#pragma unroll
    for (int i = 0; i < 4; i++) {
        int q = q0 + ty*4 + i;
        float4 v; v.x = acc[i][0]; v.y = acc[i][1]; v.z = acc[i][2]; v.w = acc[i][3];
        *(float4*)&g_ctx[(size_t)(b*LQ + q) * Hh + h*HD + tx*4] = v;
    }
}

// ---------------- layernorm over last dim ----------------
__global__ __launch_bounds__(256) void ln_kernel(
    const float* __restrict__ Y, const float* __restrict__ w,
    const float* __restrict__ bta, float* __restrict__ out)
{
    const int row = blockIdx.x;
    __shared__ float buf[Hh];
    __shared__ float red[256];
    const int tid = threadIdx.x;
    const float* y = Y + (size_t)row * Hh;

    float s = 0.f;
    for (int i = tid; i < Hh; i += 256) { float v = y[i]; buf[i] = v; s += v; }
    red[tid] = s; __syncthreads();
    for (int st = 128; st > 0; st >>= 1) {
        if (tid < st) red[tid] += red[tid + st];
        __syncthreads();
    }
    const float mu = red[0] * (1.0f / Hh); __syncthreads();

    float vs = 0.f;
    for (int i = tid; i < Hh; i += 256) { float d = buf[i] - mu; vs += d * d; }
    red[tid] = vs; __syncthreads();
    for (int st = 128; st > 0; st >>= 1) {
        if (tid < st) red[tid] += red[tid + st];
        __syncthreads();
    }
    const float inv = rsqrtf(red[0] * (1.0f / Hh) + LN_EPS);

    for (int i = tid; i < Hh; i += 256)
        out[(size_t)row * Hh + i] = (buf[i] - mu) * inv * w[i] + bta[i];
}

// ---------------- launch ----------------
extern "C" void kernel_launch(void* const* d_in, const int* in_sizes, int n_in,
                              void* d_out, int out_size)
{
    (void)in_sizes; (void)n_in; (void)out_size;
    const float* hs   = (const float*)d_in[0];
    const float* ehs  = (const float*)d_in[1];
    const int*   mask = (const int*)  d_in[2];
    const float* q_w  = (const float*)d_in[3];
    const float* q_b  = (const float*)d_in[4];
    const float* k_w  = (const float*)d_in[5];
    const float* k_b  = (const float*)d_in[6];
    const float* v_w  = (const float*)d_in[7];
    const float* v_b  = (const float*)d_in[8];
    const float* o_w  = (const float*)d_in[9];
    const float* o_b  = (const float*)d_in[10];
    const float* ln_w = (const float*)d_in[11];
    const float* ln_b = (const float*)d_in[12];

    float* out  = (float*)d_out;
    float* Sout = out + (size_t)MQ * Hh;   // scores after the [2,1024,1024] out tensor

    float *pQ, *pK, *pV, *pCtx, *pY;
    cudaGetSymbolAddress((void**)&pQ,   g_Q);
    cudaGetSymbolAddress((void**)&pK,   g_K);
    cudaGetSymbolAddress((void**)&pV,   g_V);
    cudaGetSymbolAddress((void**)&pCtx, g_ctx);
    cudaGetSymbolAddress((void**)&pY,   g_y);

    // 1) projections
    gemm_nt_bias<<<dim3(Hh/128, MQ/128),  256>>>(hs,  q_w, q_b, nullptr, pQ, MQ,  Hh, Hh);
    gemm_nt_bias<<<dim3(Hh/128, MKV/128), 256>>>(ehs, k_w, k_b, nullptr, pK, MKV, Hh, Hh);
    gemm_nt_bias<<<dim3(Hh/128, MKV/128), 256>>>(ehs, v_w, v_b, nullptr, pV, MKV, Hh, Hh);

    // 2) masked scores -> second output tensor
    scores_kernel<<<dim3(LKV/64, LQ/64, Bb*NHh), 256>>>(mask, Sout);

    // 3) softmax row stats
    rowstats_kernel<<<NROWS, 256>>>(Sout);

    // 4) ctx = softmax(S) @ V
    ctx_kernel<<<dim3(LQ/64, Bb*NHh), 256>>>(Sout);

    // 5) O-projection + residual
    gemm_nt_bias<<<dim3(Hh/128, MQ/128), 256>>>(pCtx, o_w, o_b, hs, pY, MQ, Hh, Hh);

    // 6) layernorm -> first output tensor
    ln_kernel<<<MQ, 256>>>(pY, ln_w, ln_b, out);
}

// round 11
// speedup vs baseline: 1.5630x; 1.5630x over previous
#include <cuda_runtime.h>
#include <cuda_bf16.h>
#include <math.h>
#include <stdint.h>

#define Bb 2
#define LQ 1024
#define LKV 4096
#define Hh 1024
#define NHh 16
#define HD 64
#define MQ (Bb*LQ)        // 2048
#define MKV (Bb*LKV)      // 8192
#define NROWS (Bb*NHh*LQ) // 32768
#define LN_EPS 1e-12f
#define NEG_INF __int_as_float(0xff800000)

// ---------------- scratch (device globals; no allocation) ----------------
__device__ float g_Q[MQ*Hh];
__device__ float g_K[MKV*Hh];
__device__ float g_V[MKV*Hh];
__device__ float g_ctx[MQ*Hh];
__device__ float g_y[MQ*Hh];
__device__ float g_rmax[NROWS];
__device__ float g_rinv[NROWS];
// bf16 split buffers (K' = 3K trick: [hi|lo|hi] x [hi|hi|lo])
__device__ __nv_bfloat16 g_Xq2 [MQ  * 3072];
__device__ __nv_bfloat16 g_Xkv2[MKV * 3072];
__device__ __nv_bfloat16 g_Xo2 [MQ  * 3072];
__device__ __nv_bfloat16 g_Wq2 [Hh * 3072];
__device__ __nv_bfloat16 g_Wk2 [Hh * 3072];
__device__ __nv_bfloat16 g_Wv2 [Hh * 3072];
__device__ __nv_bfloat16 g_Wo2 [Hh * 3072];
__device__ __nv_bfloat16 g_Qh  [Bb*NHh * LQ  * 192];
__device__ __nv_bfloat16 g_Kh  [Bb*NHh * LKV * 192];
// V transposed + split: [bh][d(64)][chunk(64)][192 = hi64|hi64|lo64]
__device__ __nv_bfloat16 g_Vt  [(size_t)Bb*NHh * 64 * 64 * 192];

// ================= HMMA helper =================
__device__ __forceinline__ void mma16816(float* d, const uint32_t* a,
                                         uint32_t b0, uint32_t b1) {
    asm volatile(
        "mma.sync.aligned.m16n8k16.row.col.f32.bf16.bf16.f32 "
        "{%0,%1,%2,%3}, {%4,%5,%6,%7}, {%8,%9}, {%0,%1,%2,%3};"
        : "+f"(d[0]), "+f"(d[1]), "+f"(d[2]), "+f"(d[3])
        : "r"(a[0]), "r"(a[1]), "r"(a[2]), "r"(a[3]), "r"(b0), "r"(b1));
}

// ================= HMMA GEMM =================
// out[m][n] = sum_{k<nc*64} A[m][k]*B[n][k]  (NT, bf16 in, fp32 out)
// mode 0: + bias[n] (+ res[m][n] if res)
// mode 1: scores epilogue: *0.125 with mask -> -inf
#define GP 72   // padded smem row (bf16)
__global__ __launch_bounds__(256) void hmma_gemm(
    const __nv_bfloat16* __restrict__ A, const __nv_bfloat16* __restrict__ B,
    int lda, int nc,
    const float* __restrict__ bias, const float* __restrict__ res,
    const int* __restrict__ mask,
    float* __restrict__ out, int ldo, int mode,
    size_t strA, size_t strB, size_t strO)
{
    __shared__ __nv_bfloat16 As[128*GP];
    __shared__ __nv_bfloat16 Bs[128*GP];
    __shared__ float stage[128];
    const int tid = threadIdx.x, warp = tid >> 5, lane = tid & 31;
    const int m0 = blockIdx.y * 128, n0 = blockIdx.x * 128, z = blockIdx.z;

    const __nv_bfloat16* Ap = A + (size_t)z * strA + (size_t)m0 * lda;
    const __nv_bfloat16* Bp = B + (size_t)z * strB + (size_t)n0 * lda;
    float* ob = out + (size_t)z * strO;

    if (tid < 128) {
        if (mode == 0) stage[tid] = bias[n0 + tid];
        else ((int*)stage)[tid] = mask[(size_t)(z >> 4) * LKV + n0 + tid];
    }

    const int wm = (warp >> 2) * 64, wn = (warp & 3) * 32;
    const int r = lane >> 2, cq = lane & 3;

    float acc[4][4][4];
#pragma unroll
    for (int mt = 0; mt < 4; mt++)
#pragma unroll
        for (int nt = 0; nt < 4; nt++)
#pragma unroll
            for (int j = 0; j < 4; j++) acc[mt][nt][j] = 0.f;

    for (int c = 0; c < nc; c++) {
#pragma unroll
        for (int i = 0; i < 4; i++) {
            int idx = tid + i * 256;          // 0..1023
            int rr = idx >> 3, v = (idx & 7) * 8;
            *(uint4*)&As[rr*GP + v] = *(const uint4*)&Ap[(size_t)rr * lda + c*64 + v];
            *(uint4*)&Bs[rr*GP + v] = *(const uint4*)&Bp[(size_t)rr * lda + c*64 + v];
        }
        __syncthreads();
#pragma unroll
        for (int kk = 0; kk < 64; kk += 16) {
            uint32_t af[4][4];
#pragma unroll
            for (int mt = 0; mt < 4; mt++) {
                const __nv_bfloat16* ab = &As[(wm + mt*16 + r)*GP + kk + cq*2];
                af[mt][0] = *(const uint32_t*)(ab);
                af[mt][1] = *(const uint32_t*)(ab + 8*GP);
                af[mt][2] = *(const uint32_t*)(ab + 8);
                af[mt][3] = *(const uint32_t*)(ab + 8*GP + 8);
            }
#pragma unroll
            for (int nt = 0; nt < 4; nt++) {
                const __nv_bfloat16* bb = &Bs[(wn + nt*8 + r)*GP + kk + cq*2];
                uint32_t b0 = *(const uint32_t*)(bb);
                uint32_t b1 = *(const uint32_t*)(bb + 8);
#pragma unroll
                for (int mt = 0; mt < 4; mt++)
                    mma16816(acc[mt][nt], af[mt], b0, b1);
            }
        }
        __syncthreads();
    }

    // epilogue
#pragma unroll
    for (int mt = 0; mt < 4; mt++) {
        const int mA = m0 + wm + mt*16 + r;
#pragma unroll
        for (int nt = 0; nt < 4; nt++) {
            const int nl = wn + nt*8 + cq*2;
            const int nA = n0 + nl;
            if (mode == 0) {
                float bx = stage[nl], by = stage[nl + 1];
                float2 v0, v1;
                v0.x = acc[mt][nt][0] + bx; v0.y = acc[mt][nt][1] + by;
                v1.x = acc[mt][nt][2] + bx; v1.y = acc[mt][nt][3] + by;
                if (res) {
                    float2 r0 = *(const float2*)&res[(size_t)mA * ldo + nA];
                    float2 r1 = *(const float2*)&res[(size_t)(mA+8) * ldo + nA];
                    v0.x += r0.x; v0.y += r0.y; v1.x += r1.x; v1.y += r1.y;
                }
                *(float2*)&ob[(size_t)mA * ldo + nA]     = v0;
                *(float2*)&ob[(size_t)(mA+8) * ldo + nA] = v1;
            } else {
                int mx = ((int*)stage)[nl], my = ((int*)stage)[nl + 1];
                float2 v0, v1;
                v0.x = mx ? acc[mt][nt][0] * 0.125f : NEG_INF;
                v0.y = my ? acc[mt][nt][1] * 0.125f : NEG_INF;
                v1.x = mx ? acc[mt][nt][2] * 0.125f : NEG_INF;
                v1.y = my ? acc[mt][nt][3] * 0.125f : NEG_INF;
                *(float2*)&ob[(size_t)mA * ldo + nA]     = v0;
                *(float2*)&ob[(size_t)(mA+8) * ldo + nA] = v1;
            }
        }
    }
}

// ================= split kernels =================
__global__ __launch_bounds__(256) void split_ab(const float* __restrict__ in,
                                                __nv_bfloat16* __restrict__ out, int modeB)
{
    size_t e = ((size_t)blockIdx.x * 256 + threadIdx.x) * 4;
    size_t rr = e >> 10, c = e & 1023;
    float4 v = *(const float4*)(in + e);
    float vv[4] = {v.x, v.y, v.z, v.w};
    __nv_bfloat16 hi[4], lo[4];
#pragma unroll
    for (int j = 0; j < 4; j++) {
        hi[j] = __float2bfloat16(vv[j]);
        lo[j] = __float2bfloat16(vv[j] - __bfloat162float(hi[j]));
    }
    __nv_bfloat162 h01; h01.x = hi[0]; h01.y = hi[1];
    __nv_bfloat162 h23; h23.x = hi[2]; h23.y = hi[3];
    __nv_bfloat162 l01; l01.x = lo[0]; l01.y = lo[1];
    __nv_bfloat162 l23; l23.x = lo[2]; l23.y = lo[3];
    __nv_bfloat16* o = out + rr * 3072 + c;
    *(__nv_bfloat162*)(o + 0) = h01;       *(__nv_bfloat162*)(o + 2) = h23;
    if (modeB) {
        *(__nv_bfloat162*)(o + 1024) = h01; *(__nv_bfloat162*)(o + 1026) = h23;
        *(__nv_bfloat162*)(o + 2048) = l01; *(__nv_bfloat162*)(o + 2050) = l23;
    } else {
        *(__nv_bfloat162*)(o + 1024) = l01; *(__nv_bfloat162*)(o + 1026) = l23;
        *(__nv_bfloat162*)(o + 2048) = h01; *(__nv_bfloat162*)(o + 2050) = h23;
    }
}

__global__ __launch_bounds__(256) void split_heads(const float* __restrict__ in,
                                                   __nv_bfloat16* __restrict__ out,
                                                   int L, int modeB)
{
    size_t idx = (size_t)blockIdx.x * 256 + threadIdx.x;
    int d = (int)(idx & 63);
    int h = (int)((idx >> 6) & 15);
    size_t row = idx >> 10;
    int b = (int)(row / L), q = (int)(row % L);
    float x = in[idx];
    __nv_bfloat16 hi = __float2bfloat16(x);
    __nv_bfloat16 lo = __float2bfloat16(x - __bfloat162float(hi));
    __nv_bfloat16* o = out + (((size_t)(b * NHh + h) * L + q) * 192 + d);
    o[0]   = hi;
    o[64]  = modeB ? hi : lo;
    o[128] = modeB ? lo : hi;
}

// V fp32 [b][kv][h*64+d] -> g_Vt [bh][d][chunk][hi|hi|lo] bf16
__global__ __launch_bounds__(256) void splitT_v(const float* __restrict__ V,
                                                __nv_bfloat16* __restrict__ vt)
{
    __shared__ float t[64 * 65];
    const int bh = blockIdx.y, c = blockIdx.x;
    const int b = bh >> 4, h = bh & 15;
    const int tid = threadIdx.x;
    const float* src = V + ((size_t)b * LKV + c * 64) * Hh + h * 64;
#pragma unroll
    for (int i = 0; i < 16; i++) {
        int idx = tid + i * 256;          // 0..4095
        int kv = idx >> 6, d = idx & 63;
        t[kv * 65 + d] = src[(size_t)kv * Hh + d];
    }
    __syncthreads();
#pragma unroll
    for (int i = 0; i < 16; i++) {
        int idx = tid + i * 256;
        int d = idx >> 6, kv = idx & 63;
        float x = t[kv * 65 + d];
        __nv_bfloat16 hi = __float2bfloat16(x);
        __nv_bfloat16 lo = __float2bfloat16(x - __bfloat162float(hi));
        __nv_bfloat16* base = vt + (((size_t)bh * 64 + d) * 64 + c) * 192;
        base[kv]       = hi;
        base[64 + kv]  = hi;
        base[128 + kv] = lo;
    }
}

// ---------------- per-row softmax stats ----------------
__global__ __launch_bounds__(256) void rowstats_kernel(const float* __restrict__ S)
{
    const int row = blockIdx.x;
    const float4* s4 = (const float4*)(S + (size_t)row * LKV);
    __shared__ float red[256];
    const int tid = threadIdx.x;

    float m = NEG_INF;
    for (int i = tid; i < LKV/4; i += 256) {
        float4 v = s4[i];
        m = fmaxf(m, fmaxf(fmaxf(v.x, v.y), fmaxf(v.z, v.w)));
    }
    red[tid] = m; __syncthreads();
    for (int st = 128; st > 0; st >>= 1) {
        if (tid < st) red[tid] = fmaxf(red[tid], red[tid + st]);
        __syncthreads();
    }
    m = red[0]; __syncthreads();

    float sum = 0.f;
    for (int i = tid; i < LKV/4; i += 256) {
        float4 v = s4[i];
        sum += __expf(v.x - m) + __expf(v.y - m) + __expf(v.z - m) + __expf(v.w - m);
    }
    red[tid] = sum; __syncthreads();
    for (int st = 128; st > 0; st >>= 1) {
        if (tid < st) red[tid] += red[tid + st];
        __syncthreads();
    }
    if (tid == 0) { g_rmax[row] = m; g_rinv[row] = 1.0f / red[0]; }
}

// ---------------- ctx = softmax(S) @ V  (HMMA, fused exp) ----------------
// grid (LQ/128, 32), block 256. smem: As[128][200] + Bs[64][200] + rm/ri[128]
#define CP 200
#define CTX_SMEM (128*CP*2 + 64*CP*2 + 2*128*4)
__global__ __launch_bounds__(256) void ctx_hmma(const float* __restrict__ S,
                                                const __nv_bfloat16* __restrict__ vt)
{
    extern __shared__ char csm[];
    __nv_bfloat16* As = (__nv_bfloat16*)csm;
    __nv_bfloat16* Bs = As + 128 * CP;
    float* rm = (float*)(Bs + 64 * CP);
    float* ri = rm + 128;

    const int tid = threadIdx.x, warp = tid >> 5, lane = tid & 31;
    const int bh = blockIdx.y, q0 = blockIdx.x * 128;
    const int b = bh >> 4, h = bh & 15;
    const int rowbase = bh * LQ + q0;

    if (tid < 128) { rm[tid] = g_rmax[rowbase + tid]; ri[tid] = g_rinv[rowbase + tid]; }
    __syncthreads();

    const float* Srow = S + (size_t)rowbase * LKV;
    const __nv_bfloat16* vtb = vt + (size_t)bh * 64 * 64 * 192;
    const int wm = (warp >> 1) * 32, wn = (warp & 1) * 32;
    const int r = lane >> 2, cq = lane & 3;

    float acc[2][4][4];
#pragma unroll
    for (int mt = 0; mt < 2; mt++)
#pragma unroll
        for (int nt = 0; nt < 4; nt++)
#pragma unroll
            for (int j = 0; j < 4; j++) acc[mt][nt][j] = 0.f;

    for (int c = 0; c < 64; c++) {
        // P tile: exp(S - m) * inv -> hi/lo -> As in [hi|lo|hi] layout
#pragma unroll
        for (int i = 0; i < 8; i++) {
            int idx = tid + i * 256;       // 0..2047
            int q = idx >> 4, j = (idx & 15) * 4;
            float4 s = *(const float4*)&Srow[(size_t)q * LKV + c * 64 + j];
            float mq = rm[q], iq = ri[q];
            float p0 = __expf(s.x - mq) * iq;
            float p1 = __expf(s.y - mq) * iq;
            float p2 = __expf(s.z - mq) * iq;
            float p3 = __expf(s.w - mq) * iq;
            __nv_bfloat16 h0 = __float2bfloat16(p0), h1 = __float2bfloat16(p1);
            __nv_bfloat16 h2 = __float2bfloat16(p2), h3 = __float2bfloat16(p3);
            __nv_bfloat162 h01; h01.x = h0; h01.y = h1;
            __nv_bfloat162 h23; h23.x = h2; h23.y = h3;
            __nv_bfloat162 l01, l23;
            l01.x = __float2bfloat16(p0 - __bfloat162float(h0));
            l01.y = __float2bfloat16(p1 - __bfloat162float(h1));
            l23.x = __float2bfloat16(p2 - __bfloat162float(h2));
            l23.y = __float2bfloat16(p3 - __bfloat162float(h3));
            __nv_bfloat16* base = &As[q * CP];
            *(__nv_bfloat162*)(base + j)       = h01; *(__nv_bfloat162*)(base + j + 2)       = h23;
            *(__nv_bfloat162*)(base + 64 + j)  = l01; *(__nv_bfloat162*)(base + 64 + j + 2)  = l23;
            *(__nv_bfloat162*)(base + 128 + j) = h01; *(__nv_bfloat162*)(base + 128 + j + 2) = h23;
        }
        // V tile: 64 rows x 192 bf16 (24 x 8-elt vectors per row)
#pragma unroll
        for (int i = 0; i < 6; i++) {
            int idx = tid + i * 256;       // 0..1535
            int d = idx / 24, v = (idx % 24) * 8;
            *(uint4*)&Bs[d * CP + v] = *(const uint4*)&vtb[((size_t)d * 64 + c) * 192 + v];
        }
        __syncthreads();
#pragma unroll
        for (int kk = 0; kk < 192; kk += 16) {
            uint32_t af[2][4];
#pragma unroll
            for (int mt = 0; mt < 2; mt++) {
                const __nv_bfloat16* ab = &As[(wm + mt*16 + r) * CP + kk + cq*2];
                af[mt][0] = *(const uint32_t*)(ab);
                af[mt][1] = *(const uint32_t*)(ab + 8*CP);
                af[mt][2] = *(const uint32_t*)(ab + 8);
                af[mt][3] = *(const uint32_t*)(ab + 8*CP + 8);
            }
#pragma unroll
            for (int nt = 0; nt < 4; nt++) {
                const __nv_bfloat16* bb = &Bs[(wn + nt*8 + r) * CP + kk + cq*2];
                uint32_t b0 = *(const uint32_t*)(bb);
                uint32_t b1 = *(const uint32_t*)(bb + 8);
#pragma unroll
                for (int mt = 0; mt < 2; mt++)
                    mma16816(acc[mt][nt], af[mt], b0, b1);
            }
        }
        __syncthreads();
    }

    // epilogue: ctx [b][q][h*64 + d]
#pragma unroll
    for (int mt = 0; mt < 2; mt++) {
        const int q = q0 + wm + mt*16 + r;
#pragma unroll
        for (int nt = 0; nt < 4; nt++) {
            const int d = wn + nt*8 + cq*2;
            float2 v0, v1;
            v0.x = acc[mt][nt][0]; v0.y = acc[mt][nt][1];
            v1.x = acc[mt][nt][2]; v1.y = acc[mt][nt][3];
            *(float2*)&g_ctx[((size_t)(b*LQ + q))     * Hh + h*64 + d] = v0;
            *(float2*)&g_ctx[((size_t)(b*LQ + q + 8)) * Hh + h*64 + d] = v1;
        }
    }
}

// ---------------- layernorm over last dim ----------------
__global__ __launch_bounds__(256) void ln_kernel(
    const float* __restrict__ Y, const float* __restrict__ w,
    const float* __restrict__ bta, float* __restrict__ out)
{
    const int row = blockIdx.x;
    __shared__ float buf[Hh];
    __shared__ float red[256];
    const int tid = threadIdx.x;
    const float* y = Y + (size_t)row * Hh;

    float s = 0.f;
    for (int i = tid; i < Hh; i += 256) { float v = y[i]; buf[i] = v; s += v; }
    red[tid] = s; __syncthreads();
    for (int st = 128; st > 0; st >>= 1) {
        if (tid < st) red[tid] += red[tid + st];
        __syncthreads();
    }
    const float mu = red[0] * (1.0f / Hh); __syncthreads();

    float vs = 0.f;
    for (int i = tid; i < Hh; i += 256) { float dd = buf[i] - mu; vs += dd * dd; }
    red[tid] = vs; __syncthreads();
    for (int st = 128; st > 0; st >>= 1) {
        if (tid < st) red[tid] += red[tid + st];
        __syncthreads();
    }
    const float inv = rsqrtf(red[0] * (1.0f / Hh) + LN_EPS);

    for (int i = tid; i < Hh; i += 256)
        out[(size_t)row * Hh + i] = (buf[i] - mu) * inv * w[i] + bta[i];
}

// ---------------- launch ----------------
extern "C" void kernel_launch(void* const* d_in, const int* in_sizes, int n_in,
                              void* d_out, int out_size)
{
    (void)in_sizes; (void)n_in; (void)out_size;
    const float* hs   = (const float*)d_in[0];
    const float* ehs  = (const float*)d_in[1];
    const int*   mask = (const int*)  d_in[2];
    const float* q_w  = (const float*)d_in[3];
    const float* q_b  = (const float*)d_in[4];
    const float* k_w  = (const float*)d_in[5];
    const float* k_b  = (const float*)d_in[6];
    const float* v_w  = (const float*)d_in[7];
    const float* v_b  = (const float*)d_in[8];
    const float* o_w  = (const float*)d_in[9];
    const float* o_b  = (const float*)d_in[10];
    const float* ln_w = (const float*)d_in[11];
    const float* ln_b = (const float*)d_in[12];

    float* out  = (float*)d_out;
    float* Sout = out + (size_t)MQ * Hh;

    float *pQ, *pK, *pV, *pCtx, *pY;
    cudaGetSymbolAddress((void**)&pQ,   g_Q);
    cudaGetSymbolAddress((void**)&pK,   g_K);
    cudaGetSymbolAddress((void**)&pV,   g_V);
    cudaGetSymbolAddress((void**)&pCtx, g_ctx);
    cudaGetSymbolAddress((void**)&pY,   g_y);
    __nv_bfloat16 *pXq2, *pXkv2, *pXo2, *pWq2, *pWk2, *pWv2, *pWo2, *pQh, *pKh, *pVt;
    cudaGetSymbolAddress((void**)&pXq2,  g_Xq2);
    cudaGetSymbolAddress((void**)&pXkv2, g_Xkv2);
    cudaGetSymbolAddress((void**)&pXo2,  g_Xo2);
    cudaGetSymbolAddress((void**)&pWq2,  g_Wq2);
    cudaGetSymbolAddress((void**)&pWk2,  g_Wk2);
    cudaGetSymbolAddress((void**)&pWv2,  g_Wv2);
    cudaGetSymbolAddress((void**)&pWo2,  g_Wo2);
    cudaGetSymbolAddress((void**)&pQh,   g_Qh);
    cudaGetSymbolAddress((void**)&pKh,   g_Kh);
    cudaGetSymbolAddress((void**)&pVt,   g_Vt);

    cudaFuncSetAttribute(ctx_hmma, cudaFuncAttributeMaxDynamicSharedMemorySize, CTX_SMEM);

    // 0) precision splits
    split_ab<<<MQ,  256>>>(hs,  pXq2,  0);
    split_ab<<<MKV, 256>>>(ehs, pXkv2, 0);
    split_ab<<<Hh,  256>>>(q_w, pWq2, 1);
    split_ab<<<Hh,  256>>>(k_w, pWk2, 1);
    split_ab<<<Hh,  256>>>(v_w, pWv2, 1);
    split_ab<<<Hh,  256>>>(o_w, pWo2, 1);

    // 1) projections (HMMA)
    hmma_gemm<<<dim3(8, MQ/128,  1), 256>>>(pXq2,  pWq2, 3072, 48, q_b, nullptr, nullptr, pQ, Hh, 0, 0, 0, 0);
    hmma_gemm<<<dim3(8, MKV/128, 1), 256>>>(pXkv2, pWk2, 3072, 48, k_b, nullptr, nullptr, pK, Hh, 0, 0, 0, 0);
    hmma_gemm<<<dim3(8, MKV/128, 1), 256>>>(pXkv2, pWv2, 3072, 48, v_b, nullptr, nullptr, pV, Hh, 0, 0, 0, 0);

    // 2) head-major splits of Q, K; V transpose+split
    split_heads<<<(MQ*Hh)/256,  256>>>(pQ, pQh, LQ,  0);
    split_heads<<<(MKV*Hh)/256, 256>>>(pK, pKh, LKV, 1);
    splitT_v<<<dim3(64, Bb*NHh), 256>>>(pV, pVt);

    // 3) masked scores (HMMA, per-head batched) -> second output
    hmma_gemm<<<dim3(LKV/128, LQ/128, Bb*NHh), 256>>>(
        pQh, pKh, 192, 3, nullptr, nullptr, mask, Sout, LKV, 1,
        (size_t)LQ * 192, (size_t)LKV * 192, (size_t)LQ * LKV);

    // 4) softmax row stats
    rowstats_kernel<<<NROWS, 256>>>(Sout);

    // 5) ctx = softmax(S) @ V (HMMA, fused exp)
    ctx_hmma<<<dim3(LQ/128, Bb*NHh), 256, CTX_SMEM>>>(Sout, pVt);

    // 6) O-projection + residual (HMMA)
    split_ab<<<MQ, 256>>>(pCtx, pXo2, 0);
    hmma_gemm<<<dim3(8, MQ/128, 1), 256>>>(pXo2, pWo2, 3072, 48, o_b, hs, nullptr, pY, Hh, 0, 0, 0, 0);

    // 7) layernorm -> first output
    ln_kernel<<<MQ, 256>>>(pY, ln_w, ln_b, out);
}

// round 12
// speedup vs baseline: 2.0215x; 1.2933x over previous
#include <cuda_runtime.h>
#include <cuda_bf16.h>
#include <math.h>
#include <stdint.h>

#define Bb 2
#define LQ 1024
#define LKV 4096
#define Hh 1024
#define NHh 16
#define HD 64
#define MQ (Bb*LQ)        // 2048
#define MKV (Bb*LKV)      // 8192
#define NROWS (Bb*NHh*LQ) // 32768
#define NTILES 32         // LKV/128
#define LN_EPS 1e-12f
#define NEG_INF __int_as_float(0xff800000)

// ---------------- scratch (device globals; no allocation) ----------------
__device__ float g_Q[MQ*Hh];
__device__ float g_K[MKV*Hh];
__device__ float g_V[MKV*Hh];
__device__ float g_ctx[MQ*Hh];
__device__ float g_y[MQ*Hh];
__device__ float g_rmax[NROWS];
__device__ float g_rinv[NROWS];
__device__ float g_pmax[(size_t)NROWS*NTILES];
__device__ float g_psum[(size_t)NROWS*NTILES];
// V transposed + split: [bh][d(64)][chunk(64)][192 = hi64|hi64|lo64]
__device__ __nv_bfloat16 g_Vt[(size_t)Bb*NHh * 64 * 64 * 192];

// ================= HMMA helper =================
__device__ __forceinline__ void mma16816(float* d, const uint32_t* a,
                                         uint32_t b0, uint32_t b1) {
    asm volatile(
        "mma.sync.aligned.m16n8k16.row.col.f32.bf16.bf16.f32 "
        "{%0,%1,%2,%3}, {%4,%5,%6,%7}, {%8,%9}, {%0,%1,%2,%3};"
        : "+f"(d[0]), "+f"(d[1]), "+f"(d[2]), "+f"(d[3])
        : "r"(a[0]), "r"(a[1]), "r"(a[2]), "r"(a[3]), "r"(b0), "r"(b1));
}

// ====== fused split staging: 128 rows x 32 fp32 -> s[128][AP], 96 bf16 cols ======
// A-mode (modeB=0): [hi32|lo32|hi32], B-mode (modeB=1): [hi32|hi32|lo32]
#define AP 104
__device__ __forceinline__ void stage32(const float* __restrict__ g, int ldg,
                                        __nv_bfloat16* __restrict__ s, int modeB, int tid)
{
#pragma unroll
    for (int i = 0; i < 4; i++) {
        int idx = tid + i * 256;          // 0..1023
        int rr = idx >> 3, c4 = (idx & 7) * 4;
        float4 v = *(const float4*)&g[(size_t)rr * ldg + c4];
        float vv[4] = {v.x, v.y, v.z, v.w};
        __nv_bfloat16 hi[4], lo[4];
#pragma unroll
        for (int j = 0; j < 4; j++) {
            hi[j] = __float2bfloat16(vv[j]);
            lo[j] = __float2bfloat16(vv[j] - __bfloat162float(hi[j]));
        }
        __nv_bfloat162 h01, h23, l01, l23;
        h01.x = hi[0]; h01.y = hi[1]; h23.x = hi[2]; h23.y = hi[3];
        l01.x = lo[0]; l01.y = lo[1]; l23.x = lo[2]; l23.y = lo[3];
        __nv_bfloat16* o = s + rr * AP + c4;
        *(__nv_bfloat162*)(o)     = h01; *(__nv_bfloat162*)(o + 2)  = h23;
        if (modeB) {
            *(__nv_bfloat162*)(o + 32) = h01; *(__nv_bfloat162*)(o + 34) = h23;
            *(__nv_bfloat162*)(o + 64) = l01; *(__nv_bfloat162*)(o + 66) = l23;
        } else {
            *(__nv_bfloat162*)(o + 32) = l01; *(__nv_bfloat162*)(o + 34) = l23;
            *(__nv_bfloat162*)(o + 64) = h01; *(__nv_bfloat162*)(o + 66) = h23;
        }
    }
}

// 96-col k-loop over staged tiles: acc[4][4][4], warp tile 64x32
__device__ __forceinline__ void mma_chunk96(const __nv_bfloat16* As, const __nv_bfloat16* Bs,
                                            int wm, int wn, int r, int cq, float acc[4][4][4])
{
#pragma unroll
    for (int kk = 0; kk < 96; kk += 16) {
        uint32_t af[4][4];
#pragma unroll
        for (int mt = 0; mt < 4; mt++) {
            const __nv_bfloat16* ab = &As[(wm + mt*16 + r)*AP + kk + cq*2];
            af[mt][0] = *(const uint32_t*)(ab);
            af[mt][1] = *(const uint32_t*)(ab + 8*AP);
            af[mt][2] = *(const uint32_t*)(ab + 8);
            af[mt][3] = *(const uint32_t*)(ab + 8*AP + 8);
        }
#pragma unroll
        for (int nt = 0; nt < 4; nt++) {
            const __nv_bfloat16* bb = &Bs[(wn + nt*8 + r)*AP + kk + cq*2];
            uint32_t b0 = *(const uint32_t*)(bb);
            uint32_t b1 = *(const uint32_t*)(bb + 8);
#pragma unroll
            for (int mt = 0; mt < 4; mt++)
                mma16816(acc[mt][nt], af[mt], b0, b1);
        }
    }
}

// ================= projection GEMM (fused fp32->split staging) =================
__global__ __launch_bounds__(256) void proj_gemm(
    const float* __restrict__ X, const float* __restrict__ W,
    const float* __restrict__ bias, const float* __restrict__ res,
    float* __restrict__ out)
{
    __shared__ __nv_bfloat16 As[128*AP];
    __shared__ __nv_bfloat16 Bs[128*AP];
    __shared__ float stage[128];
    const int tid = threadIdx.x, warp = tid >> 5, lane = tid & 31;
    const int m0 = blockIdx.y * 128, n0 = blockIdx.x * 128;
    const float* Ap = X + (size_t)m0 * Hh;
    const float* Bp = W + (size_t)n0 * Hh;

    if (tid < 128) stage[tid] = bias[n0 + tid];

    const int wm = (warp >> 2) * 64, wn = (warp & 3) * 32;
    const int r = lane >> 2, cq = lane & 3;

    float acc[4][4][4];
#pragma unroll
    for (int mt = 0; mt < 4; mt++)
#pragma unroll
        for (int nt = 0; nt < 4; nt++)
#pragma unroll
            for (int j = 0; j < 4; j++) acc[mt][nt][j] = 0.f;

    for (int c = 0; c < 32; c++) {
        stage32(Ap + c*32, Hh, As, 0, tid);
        stage32(Bp + c*32, Hh, Bs, 1, tid);
        __syncthreads();
        mma_chunk96(As, Bs, wm, wn, r, cq, acc);
        __syncthreads();
    }

#pragma unroll
    for (int mt = 0; mt < 4; mt++) {
        const int mA = m0 + wm + mt*16 + r;
#pragma unroll
        for (int nt = 0; nt < 4; nt++) {
            const int nl = wn + nt*8 + cq*2;
            const int nA = n0 + nl;
            float bx = stage[nl], by = stage[nl + 1];
            float2 v0, v1;
            v0.x = acc[mt][nt][0] + bx; v0.y = acc[mt][nt][1] + by;
            v1.x = acc[mt][nt][2] + bx; v1.y = acc[mt][nt][3] + by;
            if (res) {
                float2 r0 = *(const float2*)&res[(size_t)mA * Hh + nA];
                float2 r1 = *(const float2*)&res[(size_t)(mA+8) * Hh + nA];
                v0.x += r0.x; v0.y += r0.y; v1.x += r1.x; v1.y += r1.y;
            }
            *(float2*)&out[(size_t)mA * Hh + nA]     = v0;
            *(float2*)&out[(size_t)(mA+8) * Hh + nA] = v1;
        }
    }
}

// ================= scores + per-block softmax partials =================
__global__ __launch_bounds__(256) void scores_stats(
    const float* __restrict__ Qf, const float* __restrict__ Kf,
    const int* __restrict__ mask, float* __restrict__ S,
    float* __restrict__ pmax, float* __restrict__ psum)
{
    __shared__ __nv_bfloat16 As[128*AP];
    __shared__ __nv_bfloat16 Bs[128*AP];
    __shared__ int maskS[128];
    __shared__ float rpart[4][128];
    __shared__ float bmax[128];
    const int tid = threadIdx.x, warp = tid >> 5, lane = tid & 31;
    const int kv0 = blockIdx.x * 128, q0 = blockIdx.y * 128, bh = blockIdx.z;
    const int b = bh >> 4, h = bh & 15;

    const float* Ap = Qf + ((size_t)(b*LQ  + q0 )) * Hh + h*64;
    const float* Bp = Kf + ((size_t)(b*LKV + kv0)) * Hh + h*64;
    float* Sb = S + (size_t)bh * LQ * LKV;

    if (tid < 128) maskS[tid] = mask[b*LKV + kv0 + tid];

    const int wm = (warp >> 2) * 64, wn = (warp & 3) * 32;
    const int r = lane >> 2, cq = lane & 3;

    float acc[4][4][4];
#pragma unroll
    for (int mt = 0; mt < 4; mt++)
#pragma unroll
        for (int nt = 0; nt < 4; nt++)
#pragma unroll
            for (int j = 0; j < 4; j++) acc[mt][nt][j] = 0.f;

    for (int c = 0; c < 2; c++) {
        stage32(Ap + c*32, Hh, As, 0, tid);
        stage32(Bp + c*32, Hh, Bs, 1, tid);
        __syncthreads();
        mma_chunk96(As, Bs, wm, wn, r, cq, acc);
        __syncthreads();
    }

#pragma unroll
    for (int mt = 0; mt < 4; mt++) {
        const int lm = wm + mt*16 + r;
#pragma unroll
        for (int nt = 0; nt < 4; nt++) {
            const int nl = wn + nt*8 + cq*2;
            int mx = maskS[nl], my = maskS[nl + 1];
            acc[mt][nt][0] = mx ? acc[mt][nt][0] * 0.125f : NEG_INF;
            acc[mt][nt][1] = my ? acc[mt][nt][1] * 0.125f : NEG_INF;
            acc[mt][nt][2] = mx ? acc[mt][nt][2] * 0.125f : NEG_INF;
            acc[mt][nt][3] = my ? acc[mt][nt][3] * 0.125f : NEG_INF;
            float2 v0, v1;
            v0.x = acc[mt][nt][0]; v0.y = acc[mt][nt][1];
            v1.x = acc[mt][nt][2]; v1.y = acc[mt][nt][3];
            *(float2*)&Sb[(size_t)(q0 + lm)     * LKV + kv0 + nl] = v0;
            *(float2*)&Sb[(size_t)(q0 + lm + 8) * LKV + kv0 + nl] = v1;
        }
    }

#pragma unroll
    for (int mt = 0; mt < 4; mt++) {
#pragma unroll
        for (int half = 0; half < 2; half++) {
            float mrow = NEG_INF;
#pragma unroll
            for (int nt = 0; nt < 4; nt++) {
                mrow = fmaxf(mrow, acc[mt][nt][2*half + 0]);
                mrow = fmaxf(mrow, acc[mt][nt][2*half + 1]);
            }
            mrow = fmaxf(mrow, __shfl_xor_sync(0xFFFFFFFF, mrow, 1));
            mrow = fmaxf(mrow, __shfl_xor_sync(0xFFFFFFFF, mrow, 2));
            if (cq == 0) rpart[warp & 3][wm + mt*16 + r + half*8] = mrow;
        }
    }
    __syncthreads();
    if (tid < 128)
        bmax[tid] = fmaxf(fmaxf(rpart[0][tid], rpart[1][tid]),
                          fmaxf(rpart[2][tid], rpart[3][tid]));
    __syncthreads();

#pragma unroll
    for (int mt = 0; mt < 4; mt++) {
#pragma unroll
        for (int half = 0; half < 2; half++) {
            const int row = wm + mt*16 + r + half*8;
            const float bm = bmax[row];
            float srow = 0.f;
#pragma unroll
            for (int nt = 0; nt < 4; nt++) {
#pragma unroll
                for (int j = 0; j < 2; j++) {
                    float v = acc[mt][nt][2*half + j];
                    srow += (v == NEG_INF) ? 0.f : __expf(v - bm);
                }
            }
            srow += __shfl_xor_sync(0xFFFFFFFF, srow, 1);
            srow += __shfl_xor_sync(0xFFFFFFFF, srow, 2);
            if (cq == 0) rpart[warp & 3][row] = srow;
        }
    }
    __syncthreads();
    if (tid < 128) {
        float ssum = rpart[0][tid] + rpart[1][tid] + rpart[2][tid] + rpart[3][tid];
        size_t grow = (size_t)bh * LQ + q0 + tid;
        pmax[grow * NTILES + blockIdx.x] = bmax[tid];
        psum[grow * NTILES + blockIdx.x] = ssum;
    }
}

// ================= combine partial stats =================
__global__ __launch_bounds__(256) void stats_reduce(
    const float* __restrict__ pmax, const float* __restrict__ psum)
{
    const int row = blockIdx.x * 8 + (threadIdx.x >> 5);
    const int lane = threadIdx.x & 31;
    float pm = pmax[(size_t)row * NTILES + lane];
    float ps = psum[(size_t)row * NTILES + lane];
    float m = pm;
#pragma unroll
    for (int off = 16; off > 0; off >>= 1)
        m = fmaxf(m, __shfl_xor_sync(0xFFFFFFFF, m, off));
    float term = (ps > 0.f) ? ps * __expf(pm - m) : 0.f;
#pragma unroll
    for (int off = 16; off > 0; off >>= 1)
        term += __shfl_xor_sync(0xFFFFFFFF, term, off);
    if (lane == 0) { g_rmax[row] = m; g_rinv[row] = 1.0f / term; }
}

// ================= V transpose + split =================
__global__ __launch_bounds__(256) void splitT_v(const float* __restrict__ V,
                                                __nv_bfloat16* __restrict__ vt)
{
    __shared__ float t[64 * 65];
    const int bh = blockIdx.y, c = blockIdx.x;
    const int b = bh >> 4, h = bh & 15;
    const int tid = threadIdx.x;
    const float* src = V + ((size_t)b * LKV + c * 64) * Hh + h * 64;
#pragma unroll
    for (int i = 0; i < 16; i++) {
        int idx = tid + i * 256;
        int kv = idx >> 6, d = idx & 63;
        t[kv * 65 + d] = src[(size_t)kv * Hh + d];
    }
    __syncthreads();
#pragma unroll
    for (int i = 0; i < 16; i++) {
        int idx = tid + i * 256;
        int d = idx >> 6, kv = idx & 63;
        float x = t[kv * 65 + d];
        __nv_bfloat16 hi = __float2bfloat16(x);
        __nv_bfloat16 lo = __float2bfloat16(x - __bfloat162float(hi));
        __nv_bfloat16* base = vt + (((size_t)bh * 64 + d) * 64 + c) * 192;
        base[kv]       = hi;
        base[64 + kv]  = hi;
        base[128 + kv] = lo;
    }
}

// ---------------- ctx = softmax(S) @ V  (HMMA, fused exp) ----------------
#define CP 200
#define CTX_SMEM (128*CP*2 + 64*CP*2 + 2*128*4)
__global__ __launch_bounds__(256) void ctx_hmma(const float* __restrict__ S,
                                                const __nv_bfloat16* __restrict__ vt)
{
    extern __shared__ char csm[];
    __nv_bfloat16* As = (__nv_bfloat16*)csm;
    __nv_bfloat16* Bs = As + 128 * CP;
    float* rm = (float*)(Bs + 64 * CP);
    float* ri = rm + 128;

    const int tid = threadIdx.x, warp = tid >> 5, lane = tid & 31;
    const int bh = blockIdx.y, q0 = blockIdx.x * 128;
    const int b = bh >> 4, h = bh & 15;
    const int rowbase = bh * LQ + q0;

    if (tid < 128) { rm[tid] = g_rmax[rowbase + tid]; ri[tid] = g_rinv[rowbase + tid]; }
    __syncthreads();

    const float* Srow = S + (size_t)rowbase * LKV;
    const __nv_bfloat16* vtb = vt + (size_t)bh * 64 * 64 * 192;
    const int wm = (warp >> 1) * 32, wn = (warp & 1) * 32;
    const int r = lane >> 2, cq = lane & 3;

    float acc[2][4][4];
#pragma unroll
    for (int mt = 0; mt < 2; mt++)
#pragma unroll
        for (int nt = 0; nt < 4; nt++)
#pragma unroll
            for (int j = 0; j < 4; j++) acc[mt][nt][j] = 0.f;

    for (int c = 0; c < 64; c++) {
#pragma unroll
        for (int i = 0; i < 8; i++) {
            int idx = tid + i * 256;
            int q = idx >> 4, j = (idx & 15) * 4;
            float4 s = *(const float4*)&Srow[(size_t)q * LKV + c * 64 + j];
            float mq = rm[q], iq = ri[q];
            float p0 = __expf(s.x - mq) * iq;
            float p1 = __expf(s.y - mq) * iq;
            float p2 = __expf(s.z - mq) * iq;
            float p3 = __expf(s.w - mq) * iq;
            __nv_bfloat16 h0 = __float2bfloat16(p0), h1 = __float2bfloat16(p1);
            __nv_bfloat16 h2 = __float2bfloat16(p2), h3 = __float2bfloat16(p3);
            __nv_bfloat162 h01; h01.x = h0; h01.y = h1;
            __nv_bfloat162 h23; h23.x = h2; h23.y = h3;
            __nv_bfloat162 l01, l23;
            l01.x = __float2bfloat16(p0 - __bfloat162float(h0));
            l01.y = __float2bfloat16(p1 - __bfloat162float(h1));
            l23.x = __float2bfloat16(p2 - __bfloat162float(h2));
            l23.y = __float2bfloat16(p3 - __bfloat162float(h3));
            __nv_bfloat16* base = &As[q * CP];
            *(__nv_bfloat162*)(base + j)       = h01; *(__nv_bfloat162*)(base + j + 2)       = h23;
            *(__nv_bfloat162*)(base + 64 + j)  = l01; *(__nv_bfloat162*)(base + 64 + j + 2)  = l23;
            *(__nv_bfloat162*)(base + 128 + j) = h01; *(__nv_bfloat162*)(base + 128 + j + 2) = h23;
        }
#pragma unroll
        for (int i = 0; i < 6; i++) {
            int idx = tid + i * 256;
            int d = idx / 24, v = (idx % 24) * 8;
            *(uint4*)&Bs[d * CP + v] = *(const uint4*)&vtb[((size_t)d * 64 + c) * 192 + v];
        }
        __syncthreads();
#pragma unroll
        for (int kk = 0; kk < 192; kk += 16) {
            uint32_t af[2][4];
#pragma unroll
            for (int mt = 0; mt < 2; mt++) {
                const __nv_bfloat16* ab = &As[(wm + mt*16 + r) * CP + kk + cq*2];
                af[mt][0] = *(const uint32_t*)(ab);
                af[mt][1] = *(const uint32_t*)(ab + 8*CP);
                af[mt][2] = *(const uint32_t*)(ab + 8);
                af[mt][3] = *(const uint32_t*)(ab + 8*CP + 8);
            }
#pragma unroll
            for (int nt = 0; nt < 4; nt++) {
                const __nv_bfloat16* bb = &Bs[(wn + nt*8 + r) * CP + kk + cq*2];
                uint32_t b0 = *(const uint32_t*)(bb);
                uint32_t b1 = *(const uint32_t*)(bb + 8);
#pragma unroll
                for (int mt = 0; mt < 2; mt++)
                    mma16816(acc[mt][nt], af[mt], b0, b1);
            }
        }
        __syncthreads();
    }

#pragma unroll
    for (int mt = 0; mt < 2; mt++) {
        const int q = q0 + wm + mt*16 + r;
#pragma unroll
        for (int nt = 0; nt < 4; nt++) {
            const int d = wn + nt*8 + cq*2;
            float2 v0, v1;
            v0.x = acc[mt][nt][0]; v0.y = acc[mt][nt][1];
            v1.x = acc[mt][nt][2]; v1.y = acc[mt][nt][3];
            *(float2*)&g_ctx[((size_t)(b*LQ + q))     * Hh + h*64 + d] = v0;
            *(float2*)&g_ctx[((size_t)(b*LQ + q + 8)) * Hh + h*64 + d] = v1;
        }
    }
}

// ---------------- layernorm over last dim ----------------
__global__ __launch_bounds__(256) void ln_kernel(
    const float* __restrict__ Y, const float* __restrict__ w,
    const float* __restrict__ bta, float* __restrict__ out)
{
    const int row = blockIdx.x;
    __shared__ float buf[Hh];
    __shared__ float red[256];
    const int tid = threadIdx.x;
    const float* y = Y + (size_t)row * Hh;

    float s = 0.f;
    for (int i = tid; i < Hh; i += 256) { float v = y[i]; buf[i] = v; s += v; }
    red[tid] = s; __syncthreads();
    for (int st = 128; st > 0; st >>= 1) {
        if (tid < st) red[tid] += red[tid + st];
        __syncthreads();
    }
    const float mu = red[0] * (1.0f / Hh); __syncthreads();

    float vs = 0.f;
    for (int i = tid; i < Hh; i += 256) { float dd = buf[i] - mu; vs += dd * dd; }
    red[tid] = vs; __syncthreads();
    for (int st = 128; st > 0; st >>= 1) {
        if (tid < st) red[tid] += red[tid + st];
        __syncthreads();
    }
    const float inv = rsqrtf(red[0] * (1.0f / Hh) + LN_EPS);

    for (int i = tid; i < Hh; i += 256)
        out[(size_t)row * Hh + i] = (buf[i] - mu) * inv * w[i] + bta[i];
}

// ---------------- launch ----------------
extern "C" void kernel_launch(void* const* d_in, const int* in_sizes, int n_in,
                              void* d_out, int out_size)
{
    (void)in_sizes; (void)n_in; (void)out_size;
    const float* hs   = (const float*)d_in[0];
    const float* ehs  = (const float*)d_in[1];
    const int*   mask = (const int*)  d_in[2];
    const float* q_w  = (const float*)d_in[3];
    const float* q_b  = (const float*)d_in[4];
    const float* k_w  = (const float*)d_in[5];
    const float* k_b  = (const float*)d_in[6];
    const float* v_w  = (const float*)d_in[7];
    const float* v_b  = (const float*)d_in[8];
    const float* o_w  = (const float*)d_in[9];
    const float* o_b  = (const float*)d_in[10];
    const float* ln_w = (const float*)d_in[11];
    const float* ln_b = (const float*)d_in[12];

    float* out  = (float*)d_out;
    float* Sout = out + (size_t)MQ * Hh;

    float *pQ, *pK, *pV, *pCtx, *pY, *pPmax, *pPsum;
    cudaGetSymbolAddress((void**)&pQ,    g_Q);
    cudaGetSymbolAddress((void**)&pK,    g_K);
    cudaGetSymbolAddress((void**)&pV,    g_V);
    cudaGetSymbolAddress((void**)&pCtx,  g_ctx);
    cudaGetSymbolAddress((void**)&pY,    g_y);
    cudaGetSymbolAddress((void**)&pPmax, g_pmax);
    cudaGetSymbolAddress((void**)&pPsum, g_psum);
    __nv_bfloat16* pVt;
    cudaGetSymbolAddress((void**)&pVt, g_Vt);

    cudaFuncSetAttribute(ctx_hmma, cudaFuncAttributeMaxDynamicSharedMemorySize, CTX_SMEM);

    // 1) projections (HMMA, fused fp32->split staging)
    proj_gemm<<<dim3(8, MQ/128),  256>>>(hs,  q_w, q_b, nullptr, pQ);
    proj_gemm<<<dim3(8, MKV/128), 256>>>(ehs, k_w, k_b, nullptr, pK);
    proj_gemm<<<dim3(8, MKV/128), 256>>>(ehs, v_w, v_b, nullptr, pV);

    // 2) V transpose + split
    splitT_v<<<dim3(64, Bb*NHh), 256>>>(pV, pVt);

    // 3) masked scores + softmax partials -> second output + pmax/psum
    scores_stats<<<dim3(NTILES, LQ/128, Bb*NHh), 256>>>(pQ, pK, mask, Sout, pPmax, pPsum);

    // 4) combine partials
    stats_reduce<<<NROWS/8, 256>>>(pPmax, pPsum);

    // 5) ctx = softmax(S) @ V (HMMA, fused exp)
    ctx_hmma<<<dim3(LQ/128, Bb*NHh), 256, CTX_SMEM>>>(Sout, pVt);

    // 6) O-projection + residual
    proj_gemm<<<dim3(8, MQ/128), 256>>>(pCtx, o_w, o_b, hs, pY);

    // 7) layernorm -> first output
    ln_kernel<<<MQ, 256>>>(pY, ln_w, ln_b, out);
}